// round 13
// baseline (speedup 1.0000x reference)
#include <cuda_runtime.h>
#include <math.h>

// ---------------------------------------------------------------------------
// EdgeGatedMPNNLayer — GB300 (sm_103a) — Round 13
//  * GEMM kernels: 512 threads, 4 rows/thread, __launch_bounds__(512,2)
//    -> 32 warps/SM (was 16). Same FFMA2 core, same 64x128 tile.
//  * Edge kernel unchanged from R12 (gelu_fast + RED.v4, 2-edge unroll).
// ---------------------------------------------------------------------------

#define DIM 128
#define MAXN 50000
#define EPS 1e-5f

#define BM 64
#define XSTR 128
#define SMEM_BYTES ((DIM*DIM + BM*XSTR)*4)   // 96KB -> 2 CTA/SM

typedef unsigned long long u64;

__device__ float g_xj [MAXN*DIM];
__device__ float g_A  [MAXN*DIM];
__device__ float g_B  [MAXN*DIM];
__device__ float g_agg[MAXN*DIM];
__device__ float g_params[3*DIM];   // we0[128], we1[128], cbias[128]

__device__ __forceinline__ float gelu_exact(float v) {
    return 0.5f * v * (1.0f + erff(v * 0.70710678118654752f));
}
// tanh-form GELU via MUFU.TANH (gate path only)
__device__ __forceinline__ float gelu_fast(float v) {
    float u = v * fmaf(0.035677408136f, v * v, 0.79788456080f);
    float t;
    asm("tanh.approx.f32 %0, %1;" : "=f"(t) : "f"(u));
    return 0.5f * v * (1.0f + t);
}

__device__ __forceinline__ void red_add_v4(float* p, float a, float b, float c, float d) {
    asm volatile("red.global.add.v4.f32 [%0], {%1,%2,%3,%4};"
                 :: "l"(p), "f"(a), "f"(b), "f"(c), "f"(d) : "memory");
}

__device__ __forceinline__ u64 pack2(float a, float b) {
    u64 r; asm("mov.b64 %0, {%1, %2};" : "=l"(r) : "f"(a), "f"(b)); return r;
}
__device__ __forceinline__ void fma2(u64& d, u64 a, u64 b) {
    asm("fma.rn.f32x2 %0, %1, %2, %0;" : "+l"(d) : "l"(a), "l"(b));
}
__device__ __forceinline__ float2 unpack2(u64 v) {
    float2 r; asm("mov.b64 {%0, %1}, %2;" : "=f"(r.x), "=f"(r.y) : "l"(v)); return r;
}

// ---------------------------------------------------------------------------
// GEMM core, 4 rows/thread (FFMA2): conflict-free LDS.128 on W, broadcast X.
// ---------------------------------------------------------------------------
__device__ __forceinline__ void gemm_core4(const float* __restrict__ Ws,
                                           const float* __restrict__ Xs,
                                           int lane, int r0, u64 acc[4][2])
{
    #pragma unroll 2
    for (int k4 = 0; k4 < 32; k4++) {
        u64 w[4][2];
        #pragma unroll
        for (int kk = 0; kk < 4; kk++) {
            ulonglong2 wv = *(const ulonglong2*)(Ws + (k4*4 + kk)*DIM + lane*4);
            w[kk][0] = wv.x; w[kk][1] = wv.y;
        }
        #pragma unroll
        for (int i = 0; i < 4; i++) {
            float4 xq = *(const float4*)(Xs + (r0 + i)*XSTR + k4*4);
            u64 x0 = pack2(xq.x, xq.x);
            u64 x1 = pack2(xq.y, xq.y);
            u64 x2 = pack2(xq.z, xq.z);
            u64 x3 = pack2(xq.w, xq.w);
            fma2(acc[i][0], x0, w[0][0]); fma2(acc[i][1], x0, w[0][1]);
            fma2(acc[i][0], x1, w[1][0]); fma2(acc[i][1], x1, w[1][1]);
            fma2(acc[i][0], x2, w[2][0]); fma2(acc[i][1], x2, w[2][1]);
            fma2(acc[i][0], x3, w[3][0]); fma2(acc[i][1], x3, w[3][1]);
        }
    }
}

__device__ __forceinline__ void load_W_tile(float* Ws, const float* __restrict__ W, int t)
{
    const float4* Wv  = (const float4*)W;
    float4*       Wsv = (float4*)Ws;
    #pragma unroll
    for (int i = 0; i < 8; i++) Wsv[t + i*512] = Wv[t + i*512];
}

__device__ __forceinline__ void load_X_tile(float* Xs, const float* __restrict__ src,
                                            int t, int m0, int M)
{
    #pragma unroll
    for (int i = 0; i < 4; i++) {
        int idx = t + i*512;               // float4 index; row = idx>>5 (XSTR==DIM)
        int grow = m0 + (idx >> 5);
        float4 v = make_float4(0.f, 0.f, 0.f, 0.f);
        if (grow < M) v = ((const float4*)src)[(size_t)m0*32 + idx];
        ((float4*)Xs)[idx] = v;
    }
}

// ---------------------------------------------------------------------------
__global__ void param_kernel(const float* __restrict__ Wg1, const float* __restrict__ bg1,
                             const float* __restrict__ bng, const float* __restrict__ bnb,
                             const float* __restrict__ bnm, const float* __restrict__ bnv)
{
    int n = threadIdx.x;
    if (n < DIM) {
        float s = bng[n] * rsqrtf(bnv[n] + EPS);
        g_params[n]         = Wg1[256*DIM + n] * s;
        g_params[DIM + n]   = Wg1[257*DIM + n] * s;
        g_params[2*DIM + n] = bg1[n]*s + (bnb[n] - bnm[n]*s);
    }
}

// ---------------------------------------------------------------------------
// Fused node GEMMs: xj = x@Wphi + bphi; A = (x@Wg1[:128])*s; B = (x@Wg1[128:])*s
// ---------------------------------------------------------------------------
__global__ void __launch_bounds__(512, 2) node_fused(
    const float* __restrict__ x,
    const float* __restrict__ Wphi, const float* __restrict__ bphi,
    const float* __restrict__ Wg1,
    const float* __restrict__ bng,  const float* __restrict__ bnv,
    int M)
{
    extern __shared__ float sm[];
    float* Ws = sm;
    float* Xs = sm + DIM*DIM;

    int t = threadIdx.x, lane = t & 31, warp = t >> 5;
    int m0 = blockIdx.x * BM, r0 = warp * 4;
    int c0 = lane * 4;

    load_X_tile(Xs, x, t, m0, M);

    float4 g4 = *(const float4*)(bng + c0);
    float4 v4 = *(const float4*)(bnv + c0);
    float bnsc[4];
    bnsc[0] = g4.x * rsqrtf(v4.x + EPS);
    bnsc[1] = g4.y * rsqrtf(v4.y + EPS);
    bnsc[2] = g4.z * rsqrtf(v4.z + EPS);
    bnsc[3] = g4.w * rsqrtf(v4.w + EPS);
    float4 bp = *(const float4*)(bphi + c0);

    #pragma unroll 1
    for (int mode = 0; mode < 3; mode++) {
        const float* W = (mode == 0) ? Wphi : (mode == 1 ? Wg1 : Wg1 + DIM*DIM);
        float* C       = (mode == 0) ? g_xj : (mode == 1 ? g_A : g_B);

        __syncthreads();                 // Xs ready / previous compute done
        load_W_tile(Ws, W, t);
        __syncthreads();

        u64 acc[4][2];
        #pragma unroll
        for (int i = 0; i < 4; i++) { acc[i][0] = 0ull; acc[i][1] = 0ull; }

        gemm_core4(Ws, Xs, lane, r0, acc);

        float sc[4] = {1.f, 1.f, 1.f, 1.f};
        float bs[4] = {bp.x, bp.y, bp.z, bp.w};
        if (mode != 0) {
            sc[0] = bnsc[0]; sc[1] = bnsc[1]; sc[2] = bnsc[2]; sc[3] = bnsc[3];
            bs[0] = bs[1] = bs[2] = bs[3] = 0.f;
        }

        #pragma unroll
        for (int i = 0; i < 4; i++) {
            int row = m0 + r0 + i;
            if (row < M) {
                float2 p0 = unpack2(acc[i][0]);
                float2 p1 = unpack2(acc[i][1]);
                float4 v;
                v.x = fmaf(p0.x, sc[0], bs[0]);
                v.y = fmaf(p0.y, sc[1], bs[1]);
                v.z = fmaf(p1.x, sc[2], bs[2]);
                v.w = fmaf(p1.y, sc[3], bs[3]);
                ((float4*)C)[(size_t)row*32 + lane] = v;
            }
        }
    }
}

// ---------------------------------------------------------------------------
// Edge kernel: warp per edge, 2-edge unroll; tanh-approx gelu; RED.v4 scatter.
// ---------------------------------------------------------------------------
__global__ void __launch_bounds__(256) edge_kernel(
    const int* __restrict__ ei, const float* __restrict__ ew,
    const float* __restrict__ ef, const float* __restrict__ Wg2,
    const float* __restrict__ bg2, int E)
{
    int lane = threadIdx.x & 31;
    int warp = (blockIdx.x * blockDim.x + threadIdx.x) >> 5;
    int nw   = (gridDim.x * blockDim.x) >> 5;

    float4 we0 = ((const float4*)(g_params          ))[lane];
    float4 we1 = ((const float4*)(g_params +     DIM))[lane];
    float4 cb  = ((const float4*)(g_params + 2 * DIM))[lane];
    float4 w2  = ((const float4*)Wg2)[lane];
    float  b2  = bg2[0];

    for (int e0 = warp*2; e0 < E; e0 += nw*2) {
        int e1 = e0 + 1;
        bool has1 = (e1 < E);

        int   src0 = ei[e0],       dst0 = ei[E + e0];
        int   src1 = has1 ? ei[e1] : src0;
        int   dst1 = has1 ? ei[E + e1] : dst0;
        float w_0  = ew[e0];
        float w_1  = has1 ? ew[e1] : 0.f;
        float2 ef0 = ((const float2*)ef)[e0];
        float2 ef1 = has1 ? ((const float2*)ef)[e1] : ef0;

        float4 a0 = __ldg(((const float4*)g_A)  + (size_t)dst0*32 + lane);
        float4 b0 = __ldg(((const float4*)g_B)  + (size_t)src0*32 + lane);
        float4 a1 = __ldg(((const float4*)g_A)  + (size_t)dst1*32 + lane);
        float4 b1 = __ldg(((const float4*)g_B)  + (size_t)src1*32 + lane);
        float4 x0 = __ldg(((const float4*)g_xj) + (size_t)src0*32 + lane);
        float4 x1 = __ldg(((const float4*)g_xj) + (size_t)src1*32 + lane);

        float4 h0, h1;
        h0.x = a0.x + b0.x + ef0.x*we0.x + ef0.y*we1.x + cb.x;
        h0.y = a0.y + b0.y + ef0.x*we0.y + ef0.y*we1.y + cb.y;
        h0.z = a0.z + b0.z + ef0.x*we0.z + ef0.y*we1.z + cb.z;
        h0.w = a0.w + b0.w + ef0.x*we0.w + ef0.y*we1.w + cb.w;
        h1.x = a1.x + b1.x + ef1.x*we0.x + ef1.y*we1.x + cb.x;
        h1.y = a1.y + b1.y + ef1.x*we0.y + ef1.y*we1.y + cb.y;
        h1.z = a1.z + b1.z + ef1.x*we0.z + ef1.y*we1.z + cb.z;
        h1.w = a1.w + b1.w + ef1.x*we0.w + ef1.y*we1.w + cb.w;

        float d0 = gelu_fast(h0.x)*w2.x + gelu_fast(h0.y)*w2.y
                 + gelu_fast(h0.z)*w2.z + gelu_fast(h0.w)*w2.w;
        float d1 = gelu_fast(h1.x)*w2.x + gelu_fast(h1.y)*w2.y
                 + gelu_fast(h1.z)*w2.z + gelu_fast(h1.w)*w2.w;

        #pragma unroll
        for (int off = 16; off > 0; off >>= 1) {
            d0 += __shfl_xor_sync(0xffffffffu, d0, off);
            d1 += __shfl_xor_sync(0xffffffffu, d1, off);
        }

        float c0 = w_0 / (1.f + __expf(-(d0 + b2)));
        float c1 = w_1 / (1.f + __expf(-(d1 + b2)));

        red_add_v4(g_agg + (size_t)dst0*DIM + lane*4,
                   x0.x*c0, x0.y*c0, x0.z*c0, x0.w*c0);
        if (has1)
            red_add_v4(g_agg + (size_t)dst1*DIM + lane*4,
                       x1.x*c1, x1.y*c1, x1.z*c1, x1.w*c1);
    }
}

// ---------------------------------------------------------------------------
// Update GEMM + fused epilogue (agg phase first, x phase last so Xs holds x):
//   h = gelu(x@Wu[:128] + agg@Wu[128:] + b_u); y = x + h; out = LN(y)
// ---------------------------------------------------------------------------
__global__ void __launch_bounds__(512, 2) update_kernel(
    const float* __restrict__ x, const float* __restrict__ Wu,
    const float* __restrict__ bu,
    const float* __restrict__ lng, const float* __restrict__ lnb,
    float* __restrict__ out, int M)
{
    extern __shared__ float sm[];
    float* Ws = sm;
    float* Xs = sm + DIM*DIM;

    int t = threadIdx.x, lane = t & 31, warp = t >> 5;
    int m0 = blockIdx.x * BM, r0 = warp * 4;
    int c0 = lane * 4;

    u64 acc[4][2];
    #pragma unroll
    for (int i = 0; i < 4; i++) { acc[i][0] = 0ull; acc[i][1] = 0ull; }

    #pragma unroll 1
    for (int p = 0; p < 2; p++) {
        const float* src = (p == 0) ? (const float*)g_agg : x;
        const float* W   = Wu + ((p == 0) ? DIM*DIM : 0);

        if (p) __syncthreads();          // previous compute done before overwrite
        load_W_tile(Ws, W, t);
        load_X_tile(Xs, src, t, m0, M);
        __syncthreads();

        gemm_core4(Ws, Xs, lane, r0, acc);
    }

    // epilogue: Xs holds the x tile. y = x + gelu(acc + bu), then LN per row.
    float4 bb = *(const float4*)(bu + c0);
    float av[4][4];
    float sums[4], sqs[4];

    #pragma unroll
    for (int i = 0; i < 4; i++) {
        float2 p0 = unpack2(acc[i][0]);
        float2 p1 = unpack2(acc[i][1]);
        float4 xv = *(const float4*)(Xs + (r0 + i)*XSTR + c0);
        float y0 = xv.x + gelu_exact(p0.x + bb.x);
        float y1 = xv.y + gelu_exact(p0.y + bb.y);
        float y2 = xv.z + gelu_exact(p1.x + bb.z);
        float y3 = xv.w + gelu_exact(p1.y + bb.w);
        av[i][0] = y0; av[i][1] = y1; av[i][2] = y2; av[i][3] = y3;
        sums[i] = y0 + y1 + y2 + y3;
        sqs[i]  = y0*y0 + y1*y1 + y2*y2 + y3*y3;
    }
    #pragma unroll
    for (int off = 16; off > 0; off >>= 1) {
        #pragma unroll
        for (int i = 0; i < 4; i++) {
            sums[i] += __shfl_xor_sync(0xffffffffu, sums[i], off);
            sqs[i]  += __shfl_xor_sync(0xffffffffu, sqs[i],  off);
        }
    }
    float4 lg = *(const float4*)(lng + c0);
    float4 lb = *(const float4*)(lnb + c0);

    #pragma unroll
    for (int i = 0; i < 4; i++) {
        float mu  = sums[i] * (1.f / DIM);
        float var = sqs[i] * (1.f / DIM) - mu * mu;
        float rs  = rsqrtf(var + EPS);
        int row = m0 + r0 + i;
        if (row < M) {
            float4 v;
            v.x = (av[i][0] - mu) * rs * lg.x + lb.x;
            v.y = (av[i][1] - mu) * rs * lg.y + lb.y;
            v.z = (av[i][2] - mu) * rs * lg.z + lb.z;
            v.w = (av[i][3] - mu) * rs * lg.w + lb.w;
            ((float4*)out)[(size_t)row*32 + lane] = v;
        }
    }
}

// ---------------------------------------------------------------------------
extern "C" void kernel_launch(void* const* d_in, const int* in_sizes, int n_in,
                              void* d_out, int out_size)
{
    const float* x    = (const float*)d_in[0];
    const int*   ei   = (const int*)  d_in[1];
    const float* ew   = (const float*)d_in[2];
    const float* ef   = (const float*)d_in[3];
    const float* Wphi = (const float*)d_in[5];
    const float* bphi = (const float*)d_in[6];
    const float* Wg1  = (const float*)d_in[7];
    const float* bg1  = (const float*)d_in[8];
    const float* bng  = (const float*)d_in[9];
    const float* bnb  = (const float*)d_in[10];
    const float* bnm  = (const float*)d_in[11];
    const float* bnv  = (const float*)d_in[12];
    const float* Wg2  = (const float*)d_in[13];
    const float* bg2  = (const float*)d_in[14];
    const float* Wu   = (const float*)d_in[15];
    const float* bu   = (const float*)d_in[16];
    const float* lng  = (const float*)d_in[17];
    const float* lnb  = (const float*)d_in[18];
    float* out = (float*)d_out;

    int M = in_sizes[0] / DIM;
    int E = in_sizes[2];
    if (M > MAXN) return;

    cudaFuncSetAttribute(node_fused,    cudaFuncAttributeMaxDynamicSharedMemorySize, SMEM_BYTES);
    cudaFuncSetAttribute(update_kernel, cudaFuncAttributeMaxDynamicSharedMemorySize, SMEM_BYTES);

    void* aggp = nullptr;
    cudaGetSymbolAddress(&aggp, g_agg);
    cudaMemsetAsync(aggp, 0, (size_t)M * DIM * sizeof(float), 0);

    param_kernel<<<1, DIM>>>(Wg1, bg1, bng, bnb, bnm, bnv);

    node_fused<<<(M + BM - 1) / BM, 512, SMEM_BYTES>>>(x, Wphi, bphi, Wg1, bng, bnv, M);

    edge_kernel<<<2368, 256>>>(ei, ew, ef, Wg2, bg2, E);

    update_kernel<<<(M + BM - 1) / BM, 512, SMEM_BYTES>>>(x, Wu, bu, lng, lnb, out, M);
}

// round 14
// speedup vs baseline: 1.1368x; 1.1368x over previous
#include <cuda_runtime.h>
#include <math.h>
#include <stdint.h>

// ---------------------------------------------------------------------------
// EdgeGatedMPNNLayer — GB300 (sm_103a) — Round 14
// GEMMs on mma.sync.m16n8k8 tf32 (HMMA), SINGLE-PASS everywhere (R11 showed
// ~22us/pass vs 38-45us FFMA; 3xTF32 compensation ate the win — dropped).
// smem 128KB (A + Bh only). Edge kernel = R12 (gelu_fast + RED.v4).
// ---------------------------------------------------------------------------

#define DIM 128
#define MAXN 50000
#define EPS 1e-5f

__device__ float g_xj [MAXN*DIM];
__device__ float g_A  [MAXN*DIM];
__device__ float g_B  [MAXN*DIM];
__device__ float g_agg[MAXN*DIM];
__device__ float g_params[3*DIM];          // we0, we1, cbias (edge kernel)
__device__ float g_Bh[5*DIM*DIM];          // frag-packed tf32 weight tiles

// smem float offsets for MMA kernels
#define SMF_A  0
#define SMF_BH 16384
#define SM_BYTES (32768*4)                 // 128 KB

// ---------------------------------------------------------------------------
// helpers
// ---------------------------------------------------------------------------
__device__ __forceinline__ float gelu_exact(float v) {
    return 0.5f * v * (1.0f + erff(v * 0.70710678118654752f));
}
__device__ __forceinline__ float gelu_fast(float v) {
    float u = v * fmaf(0.035677408136f, v * v, 0.79788456080f);
    float t;
    asm("tanh.approx.f32 %0, %1;" : "=f"(t) : "f"(u));
    return 0.5f * v * (1.0f + t);
}
__device__ __forceinline__ void red_add_v4(float* p, float a, float b, float c, float d) {
    asm volatile("red.global.add.v4.f32 [%0], {%1,%2,%3,%4};"
                 :: "l"(p), "f"(a), "f"(b), "f"(c), "f"(d) : "memory");
}
__device__ __forceinline__ uint32_t tf32_rd(float f) {
    uint32_t r; asm("cvt.rna.tf32.f32 %0, %1;" : "=r"(r) : "f"(f)); return r;
}
__device__ __forceinline__ void mma8(float* d, const uint32_t* a, uint32_t b0, uint32_t b1) {
    asm("mma.sync.aligned.m16n8k8.row.col.f32.tf32.tf32.f32 "
        "{%0,%1,%2,%3}, {%4,%5,%6,%7}, {%8,%9}, {%0,%1,%2,%3};"
        : "+f"(d[0]), "+f"(d[1]), "+f"(d[2]), "+f"(d[3])
        : "r"(a[0]), "r"(a[1]), "r"(a[2]), "r"(a[3]), "r"(b0), "r"(b1));
}

// fragment-packed index for A element (r, k):  [16 k8][8 m16-frag][32 lane][4 reg]
__device__ __forceinline__ int apk_idx(int r, int k) {
    return ((((k >> 3) * 8 + (r >> 4)) * 32) + (((r & 7) << 2) | (k & 3))) * 4
         + (((r >> 3) & 1) | (((k >> 2) & 1) << 1));
}
// fragment-packed index for B element (k, n):  [16 k8][8 n16-pair][32 lane][4 reg]
__device__ __forceinline__ int bpk_idx(int k, int n) {
    return ((((k >> 3) * 8 + (n >> 4)) * 32) + (((n & 7) << 2) | (k & 3))) * 4
         + (((k >> 2) & 1) | (((n >> 3) & 1) << 1));
}

// stage 128-row slab of row-major src into frag-packed smem (zero padded)
__device__ __forceinline__ void load_A_packed(float* As, const float* __restrict__ src,
                                              int t, int m0, int M) {
    #pragma unroll
    for (int i = 0; i < 16; i++) {
        int f = t + i * 256;                 // float4 index 0..4095
        int r = f >> 5, k4 = f & 31;
        float4 v = make_float4(0.f, 0.f, 0.f, 0.f);
        int gr = m0 + r;
        if (gr < M) v = ((const float4*)src)[(size_t)gr * 32 + k4];
        int k0 = k4 * 4;
        As[apk_idx(r, k0 + 0)] = v.x;
        As[apk_idx(r, k0 + 1)] = v.y;
        As[apk_idx(r, k0 + 2)] = v.z;
        As[apk_idx(r, k0 + 3)] = v.w;
    }
}
// flat copy of a pre-packed 64KB weight tile
__device__ __forceinline__ void copy_B(float* dst, const float* __restrict__ gsrc, int t) {
    const float4* s = (const float4*)gsrc;
    float4* d = (float4*)dst;
    #pragma unroll
    for (int i = 0; i < 16; i++) d[t + i * 256] = s[t + i * 256];
}

// K-loop: warp w computes rows w*16..+15 x all 128 cols. Single-pass tf32.
__device__ __forceinline__ void kloop(float acc[16][4], const float* As,
                                      const float* Bh, int w, int lane) {
    #pragma unroll 2
    for (int kk = 0; kk < 16; kk++) {
        float4 af = ((const float4*)As)[(kk * 8 + w) * 32 + lane];
        uint32_t ah[4];
        ah[0] = tf32_rd(af.x); ah[1] = tf32_rd(af.y);
        ah[2] = tf32_rd(af.z); ah[3] = tf32_rd(af.w);
        #pragma unroll
        for (int np = 0; np < 8; np++) {
            float4 bh = ((const float4*)Bh)[(kk * 8 + np) * 32 + lane];
            mma8(acc[2*np],     ah, __float_as_uint(bh.x), __float_as_uint(bh.y));
            mma8(acc[2*np + 1], ah, __float_as_uint(bh.z), __float_as_uint(bh.w));
        }
    }
}

// ---------------------------------------------------------------------------
__global__ void param_kernel(const float* __restrict__ Wg1, const float* __restrict__ bg1,
                             const float* __restrict__ bng, const float* __restrict__ bnb,
                             const float* __restrict__ bnm, const float* __restrict__ bnv)
{
    int n = threadIdx.x;
    if (n < DIM) {
        float s = bng[n] * rsqrtf(bnv[n] + EPS);
        g_params[n]         = Wg1[256*DIM + n] * s;
        g_params[DIM + n]   = Wg1[257*DIM + n] * s;
        g_params[2*DIM + n] = bg1[n]*s + (bnb[n] - bnm[n]*s);
    }
}

// Build frag-packed tf32 weight tiles. v(k,n) per mat:
// 0: Wphi | 1: Wg1[0:128]*s | 2: Wg1[128:256]*s | 3: Wu[128:256] | 4: Wu[0:128]
__global__ void prep_kernel(const float* __restrict__ Wphi, const float* __restrict__ Wg1,
                            const float* __restrict__ Wu,
                            const float* __restrict__ bng, const float* __restrict__ bnv)
{
    int mat = blockIdx.x;
    int n = threadIdx.x;
    float s = bng[n] * rsqrtf(bnv[n] + EPS);
    float* bh = g_Bh + mat * DIM * DIM;
    for (int k = 0; k < DIM; k++) {
        float v;
        if      (mat == 0) v = Wphi[k*DIM + n];
        else if (mat == 1) v = Wg1[k*DIM + n] * s;
        else if (mat == 2) v = Wg1[(128+k)*DIM + n] * s;
        else if (mat == 3) v = Wu[(128+k)*DIM + n];
        else               v = Wu[k*DIM + n];
        bh[bpk_idx(k, n)] = __uint_as_float(tf32_rd(v));
    }
}

// store acc tile to C (optional bias), rows m0+w*16..
__device__ __forceinline__ void store_tile(float* __restrict__ C, const float acc[16][4],
                                           const float* __restrict__ bias,
                                           int m0, int w, int lane, int M) {
    int r0 = w * 16 + (lane >> 2);
    int gr0 = m0 + r0, gr1 = gr0 + 8;
    #pragma unroll
    for (int nn = 0; nn < 16; nn++) {
        int c0 = nn * 8 + (lane & 3) * 2;
        float bx = 0.f, by = 0.f;
        if (bias) { float2 bb = __ldg((const float2*)(bias + c0)); bx = bb.x; by = bb.y; }
        if (gr0 < M) *(float2*)(C + (size_t)gr0 * DIM + c0)
                        = make_float2(acc[nn][0] + bx, acc[nn][1] + by);
        if (gr1 < M) *(float2*)(C + (size_t)gr1 * DIM + c0)
                        = make_float2(acc[nn][2] + bx, acc[nn][3] + by);
    }
}

// ---------------------------------------------------------------------------
// Node GEMMs: xj = x@Wphi + bphi; A = x@Wg1a*s; B = x@Wg1b*s  (all 1x tf32)
// ---------------------------------------------------------------------------
__global__ void __launch_bounds__(256) node_mma(const float* __restrict__ x,
                                               const float* __restrict__ bphi, int M)
{
    extern __shared__ float smf[];
    float* As = smf + SMF_A;
    float* Bh = smf + SMF_BH;
    int t = threadIdx.x, w = t >> 5, lane = t & 31;
    int m0 = blockIdx.x * 128;

    load_A_packed(As, x, t, m0, M);

    float acc[16][4];

    #pragma unroll 1
    for (int mode = 0; mode < 3; mode++) {
        float* C = (mode == 0) ? g_xj : (mode == 1 ? g_A : g_B);

        __syncthreads();                 // As ready / previous kloop done
        copy_B(Bh, g_Bh + mode * DIM * DIM, t);
        __syncthreads();

        #pragma unroll
        for (int i = 0; i < 16; i++) { acc[i][0]=acc[i][1]=acc[i][2]=acc[i][3]=0.f; }
        kloop(acc, As, Bh, w, lane);
        store_tile(C, acc, (mode == 0) ? bphi : (const float*)0, m0, w, lane, M);
    }
}

// ---------------------------------------------------------------------------
// Update: h = gelu(agg@Wu_hi + x@Wu_lo + bu); y = x + h; out = LN(y)*lng + lnb
// Single-pass tf32 both phases; x tile frag-packed resident for the residual.
// ---------------------------------------------------------------------------
__global__ void __launch_bounds__(256) update_mma(const float* __restrict__ x,
                                                 const float* __restrict__ bu,
                                                 const float* __restrict__ lng,
                                                 const float* __restrict__ lnb,
                                                 float* __restrict__ out, int M)
{
    extern __shared__ float smf[];
    float* As = smf + SMF_A;
    float* Bh = smf + SMF_BH;
    int t = threadIdx.x, w = t >> 5, lane = t & 31;
    int m0 = blockIdx.x * 128;

    // phase 0: agg @ Wu[128:256]
    load_A_packed(As, g_agg, t, m0, M);
    copy_B(Bh, g_Bh + 3 * DIM * DIM, t);
    __syncthreads();

    float acc[16][4];
    #pragma unroll
    for (int i = 0; i < 16; i++) { acc[i][0]=acc[i][1]=acc[i][2]=acc[i][3]=0.f; }
    kloop(acc, As, Bh, w, lane);

    // phase 1: + x @ Wu[0:128]   (x stays resident for residual)
    __syncthreads();
    load_A_packed(As, x, t, m0, M);
    copy_B(Bh, g_Bh + 4 * DIM * DIM, t);
    __syncthreads();
    kloop(acc, As, Bh, w, lane);

    // epilogue
    int r0 = w * 16 + (lane >> 2);
    int r1 = r0 + 8;
    int gr0 = m0 + r0, gr1 = m0 + r1;
    float s0 = 0.f, q0 = 0.f, s1 = 0.f, q1 = 0.f;

    #pragma unroll
    for (int nn = 0; nn < 16; nn++) {
        int c0 = nn * 8 + (lane & 3) * 2;
        float2 bb = __ldg((const float2*)(bu + c0));
        float y00 = As[apk_idx(r0, c0)]     + gelu_exact(acc[nn][0] + bb.x);
        float y01 = As[apk_idx(r0, c0 + 1)] + gelu_exact(acc[nn][1] + bb.y);
        float y10 = As[apk_idx(r1, c0)]     + gelu_exact(acc[nn][2] + bb.x);
        float y11 = As[apk_idx(r1, c0 + 1)] + gelu_exact(acc[nn][3] + bb.y);
        acc[nn][0] = y00; acc[nn][1] = y01; acc[nn][2] = y10; acc[nn][3] = y11;
        s0 += y00 + y01; q0 += y00*y00 + y01*y01;
        s1 += y10 + y11; q1 += y10*y10 + y11*y11;
    }
    // full-row reduction: 4 lanes (same lane>>2) hold each row
    s0 += __shfl_xor_sync(0xffffffffu, s0, 1); s0 += __shfl_xor_sync(0xffffffffu, s0, 2);
    q0 += __shfl_xor_sync(0xffffffffu, q0, 1); q0 += __shfl_xor_sync(0xffffffffu, q0, 2);
    s1 += __shfl_xor_sync(0xffffffffu, s1, 1); s1 += __shfl_xor_sync(0xffffffffu, s1, 2);
    q1 += __shfl_xor_sync(0xffffffffu, q1, 1); q1 += __shfl_xor_sync(0xffffffffu, q1, 2);

    float mu0 = s0 * (1.f / DIM), var0 = q0 * (1.f / DIM) - mu0 * mu0;
    float mu1 = s1 * (1.f / DIM), var1 = q1 * (1.f / DIM) - mu1 * mu1;
    float rs0 = rsqrtf(var0 + EPS), rs1 = rsqrtf(var1 + EPS);

    #pragma unroll
    for (int nn = 0; nn < 16; nn++) {
        int c0 = nn * 8 + (lane & 3) * 2;
        float2 lg = __ldg((const float2*)(lng + c0));
        float2 lb = __ldg((const float2*)(lnb + c0));
        if (gr0 < M)
            *(float2*)(out + (size_t)gr0 * DIM + c0) = make_float2(
                (acc[nn][0] - mu0) * rs0 * lg.x + lb.x,
                (acc[nn][1] - mu0) * rs0 * lg.y + lb.y);
        if (gr1 < M)
            *(float2*)(out + (size_t)gr1 * DIM + c0) = make_float2(
                (acc[nn][2] - mu1) * rs1 * lg.x + lb.x,
                (acc[nn][3] - mu1) * rs1 * lg.y + lb.y);
    }
}

// ---------------------------------------------------------------------------
// Edge kernel: warp per edge, 2-edge unroll; gelu_fast; RED.v4 scatter.
// ---------------------------------------------------------------------------
__global__ void __launch_bounds__(256) edge_kernel(
    const int* __restrict__ ei, const float* __restrict__ ew,
    const float* __restrict__ ef, const float* __restrict__ Wg2,
    const float* __restrict__ bg2, int E)
{
    int lane = threadIdx.x & 31;
    int warp = (blockIdx.x * blockDim.x + threadIdx.x) >> 5;
    int nw   = (gridDim.x * blockDim.x) >> 5;

    float4 we0 = ((const float4*)(g_params          ))[lane];
    float4 we1 = ((const float4*)(g_params +     DIM))[lane];
    float4 cb  = ((const float4*)(g_params + 2 * DIM))[lane];
    float4 w2  = ((const float4*)Wg2)[lane];
    float  b2  = bg2[0];

    for (int e0 = warp*2; e0 < E; e0 += nw*2) {
        int e1 = e0 + 1;
        bool has1 = (e1 < E);

        int   src0 = ei[e0],       dst0 = ei[E + e0];
        int   src1 = has1 ? ei[e1] : src0;
        int   dst1 = has1 ? ei[E + e1] : dst0;
        float w_0  = ew[e0];
        float w_1  = has1 ? ew[e1] : 0.f;
        float2 ef0 = ((const float2*)ef)[e0];
        float2 ef1 = has1 ? ((const float2*)ef)[e1] : ef0;

        float4 a0 = __ldg(((const float4*)g_A)  + (size_t)dst0*32 + lane);
        float4 b0 = __ldg(((const float4*)g_B)  + (size_t)src0*32 + lane);
        float4 a1 = __ldg(((const float4*)g_A)  + (size_t)dst1*32 + lane);
        float4 b1 = __ldg(((const float4*)g_B)  + (size_t)src1*32 + lane);
        float4 x0 = __ldg(((const float4*)g_xj) + (size_t)src0*32 + lane);
        float4 x1 = __ldg(((const float4*)g_xj) + (size_t)src1*32 + lane);

        float4 h0, h1;
        h0.x = a0.x + b0.x + ef0.x*we0.x + ef0.y*we1.x + cb.x;
        h0.y = a0.y + b0.y + ef0.x*we0.y + ef0.y*we1.y + cb.y;
        h0.z = a0.z + b0.z + ef0.x*we0.z + ef0.y*we1.z + cb.z;
        h0.w = a0.w + b0.w + ef0.x*we0.w + ef0.y*we1.w + cb.w;
        h1.x = a1.x + b1.x + ef1.x*we0.x + ef1.y*we1.x + cb.x;
        h1.y = a1.y + b1.y + ef1.x*we0.y + ef1.y*we1.y + cb.y;
        h1.z = a1.z + b1.z + ef1.x*we0.z + ef1.y*we1.z + cb.z;
        h1.w = a1.w + b1.w + ef1.x*we0.w + ef1.y*we1.w + cb.w;

        float d0 = gelu_fast(h0.x)*w2.x + gelu_fast(h0.y)*w2.y
                 + gelu_fast(h0.z)*w2.z + gelu_fast(h0.w)*w2.w;
        float d1 = gelu_fast(h1.x)*w2.x + gelu_fast(h1.y)*w2.y
                 + gelu_fast(h1.z)*w2.z + gelu_fast(h1.w)*w2.w;

        #pragma unroll
        for (int off = 16; off > 0; off >>= 1) {
            d0 += __shfl_xor_sync(0xffffffffu, d0, off);
            d1 += __shfl_xor_sync(0xffffffffu, d1, off);
        }

        float c0 = w_0 / (1.f + __expf(-(d0 + b2)));
        float c1 = w_1 / (1.f + __expf(-(d1 + b2)));

        red_add_v4(g_agg + (size_t)dst0*DIM + lane*4,
                   x0.x*c0, x0.y*c0, x0.z*c0, x0.w*c0);
        if (has1)
            red_add_v4(g_agg + (size_t)dst1*DIM + lane*4,
                       x1.x*c1, x1.y*c1, x1.z*c1, x1.w*c1);
    }
}

// ---------------------------------------------------------------------------
extern "C" void kernel_launch(void* const* d_in, const int* in_sizes, int n_in,
                              void* d_out, int out_size)
{
    const float* x    = (const float*)d_in[0];
    const int*   ei   = (const int*)  d_in[1];
    const float* ew   = (const float*)d_in[2];
    const float* ef   = (const float*)d_in[3];
    const float* Wphi = (const float*)d_in[5];
    const float* bphi = (const float*)d_in[6];
    const float* Wg1  = (const float*)d_in[7];
    const float* bg1  = (const float*)d_in[8];
    const float* bng  = (const float*)d_in[9];
    const float* bnb  = (const float*)d_in[10];
    const float* bnm  = (const float*)d_in[11];
    const float* bnv  = (const float*)d_in[12];
    const float* Wg2  = (const float*)d_in[13];
    const float* bg2  = (const float*)d_in[14];
    const float* Wu   = (const float*)d_in[15];
    const float* bu   = (const float*)d_in[16];
    const float* lng  = (const float*)d_in[17];
    const float* lnb  = (const float*)d_in[18];
    float* out = (float*)d_out;

    int M = in_sizes[0] / DIM;
    int E = in_sizes[2];
    if (M > MAXN) return;

    cudaFuncSetAttribute(node_mma,   cudaFuncAttributeMaxDynamicSharedMemorySize, SM_BYTES);
    cudaFuncSetAttribute(update_mma, cudaFuncAttributeMaxDynamicSharedMemorySize, SM_BYTES);

    void* aggp = nullptr;
    cudaGetSymbolAddress(&aggp, g_agg);
    cudaMemsetAsync(aggp, 0, (size_t)M * DIM * sizeof(float), 0);

    param_kernel<<<1, DIM>>>(Wg1, bg1, bng, bnb, bnm, bnv);
    prep_kernel<<<5, DIM>>>(Wphi, Wg1, Wu, bng, bnv);

    int ntiles = (M + 127) / 128;
    node_mma<<<ntiles, 256, SM_BYTES>>>(x, bphi, M);

    edge_kernel<<<2368, 256>>>(ei, ew, ef, Wg2, bg2, E);

    update_mma<<<ntiles, 256, SM_BYTES>>>(x, bu, lng, lnb, out, M);
}

// round 15
// speedup vs baseline: 1.2082x; 1.0628x over previous
#include <cuda_runtime.h>
#include <cuda_fp16.h>
#include <math.h>
#include <stdint.h>

// ---------------------------------------------------------------------------
// EdgeGatedMPNNLayer — GB300 (sm_103a) — Round 15
//  * GEMMs: single-pass tf32 mma.sync (R14 win).
//  * Edge-gathered tensors (A, B, xj) stored as fp16 (same 10-bit mantissa as
//    tf32): halves gather traffic, L2 footprint 77->38MB (stops L2 thrash).
//  * Edge kernel: 4-edge unroll for MLP; gelu_fast; RED.v4 scatter.
// ---------------------------------------------------------------------------

#define DIM 128
#define MAXN 50000
#define EPS 1e-5f

__device__ __half g_xjh[MAXN*DIM];
__device__ __half g_Ah [MAXN*DIM];
__device__ __half g_Bh2[MAXN*DIM];
__device__ float  g_agg[MAXN*DIM];
__device__ float  g_params[3*DIM];         // we0, we1, cbias (edge kernel)
__device__ float  g_Wt[5*DIM*DIM];         // frag-packed tf32 weight tiles

// smem float offsets for MMA kernels
#define SMF_A  0
#define SMF_BH 16384
#define SM_BYTES (32768*4)                 // 128 KB

// ---------------------------------------------------------------------------
__device__ __forceinline__ float gelu_exact(float v) {
    return 0.5f * v * (1.0f + erff(v * 0.70710678118654752f));
}
__device__ __forceinline__ float gelu_fast(float v) {
    float u = v * fmaf(0.035677408136f, v * v, 0.79788456080f);
    float t;
    asm("tanh.approx.f32 %0, %1;" : "=f"(t) : "f"(u));
    return 0.5f * v * (1.0f + t);
}
__device__ __forceinline__ void red_add_v4(float* p, float a, float b, float c, float d) {
    asm volatile("red.global.add.v4.f32 [%0], {%1,%2,%3,%4};"
                 :: "l"(p), "f"(a), "f"(b), "f"(c), "f"(d) : "memory");
}
__device__ __forceinline__ uint32_t tf32_rd(float f) {
    uint32_t r; asm("cvt.rna.tf32.f32 %0, %1;" : "=r"(r) : "f"(f)); return r;
}
__device__ __forceinline__ void mma8(float* d, const uint32_t* a, uint32_t b0, uint32_t b1) {
    asm("mma.sync.aligned.m16n8k8.row.col.f32.tf32.tf32.f32 "
        "{%0,%1,%2,%3}, {%4,%5,%6,%7}, {%8,%9}, {%0,%1,%2,%3};"
        : "+f"(d[0]), "+f"(d[1]), "+f"(d[2]), "+f"(d[3])
        : "r"(a[0]), "r"(a[1]), "r"(a[2]), "r"(a[3]), "r"(b0), "r"(b1));
}

// fragment-packed index for A element (r, k):  [16 k8][8 m16-frag][32 lane][4 reg]
__device__ __forceinline__ int apk_idx(int r, int k) {
    return ((((k >> 3) * 8 + (r >> 4)) * 32) + (((r & 7) << 2) | (k & 3))) * 4
         + (((r >> 3) & 1) | (((k >> 2) & 1) << 1));
}
// fragment-packed index for B element (k, n):  [16 k8][8 n16-pair][32 lane][4 reg]
__device__ __forceinline__ int bpk_idx(int k, int n) {
    return ((((k >> 3) * 8 + (n >> 4)) * 32) + (((n & 7) << 2) | (k & 3))) * 4
         + (((k >> 2) & 1) | (((n >> 3) & 1) << 1));
}

__device__ __forceinline__ void load_A_packed(float* As, const float* __restrict__ src,
                                              int t, int m0, int M) {
    #pragma unroll
    for (int i = 0; i < 16; i++) {
        int f = t + i * 256;
        int r = f >> 5, k4 = f & 31;
        float4 v = make_float4(0.f, 0.f, 0.f, 0.f);
        int gr = m0 + r;
        if (gr < M) v = ((const float4*)src)[(size_t)gr * 32 + k4];
        int k0 = k4 * 4;
        As[apk_idx(r, k0 + 0)] = v.x;
        As[apk_idx(r, k0 + 1)] = v.y;
        As[apk_idx(r, k0 + 2)] = v.z;
        As[apk_idx(r, k0 + 3)] = v.w;
    }
}
__device__ __forceinline__ void copy_B(float* dst, const float* __restrict__ gsrc, int t) {
    const float4* s = (const float4*)gsrc;
    float4* d = (float4*)dst;
    #pragma unroll
    for (int i = 0; i < 16; i++) d[t + i * 256] = s[t + i * 256];
}

// K-loop: warp w computes rows w*16..+15 x all 128 cols. Single-pass tf32.
__device__ __forceinline__ void kloop(float acc[16][4], const float* As,
                                      const float* Bh, int w, int lane) {
    #pragma unroll 2
    for (int kk = 0; kk < 16; kk++) {
        float4 af = ((const float4*)As)[(kk * 8 + w) * 32 + lane];
        uint32_t ah[4];
        ah[0] = tf32_rd(af.x); ah[1] = tf32_rd(af.y);
        ah[2] = tf32_rd(af.z); ah[3] = tf32_rd(af.w);
        #pragma unroll
        for (int np = 0; np < 8; np++) {
            float4 bh = ((const float4*)Bh)[(kk * 8 + np) * 32 + lane];
            mma8(acc[2*np],     ah, __float_as_uint(bh.x), __float_as_uint(bh.y));
            mma8(acc[2*np + 1], ah, __float_as_uint(bh.z), __float_as_uint(bh.w));
        }
    }
}

// ---------------------------------------------------------------------------
__global__ void param_kernel(const float* __restrict__ Wg1, const float* __restrict__ bg1,
                             const float* __restrict__ bng, const float* __restrict__ bnb,
                             const float* __restrict__ bnm, const float* __restrict__ bnv)
{
    int n = threadIdx.x;
    if (n < DIM) {
        float s = bng[n] * rsqrtf(bnv[n] + EPS);
        g_params[n]         = Wg1[256*DIM + n] * s;
        g_params[DIM + n]   = Wg1[257*DIM + n] * s;
        g_params[2*DIM + n] = bg1[n]*s + (bnb[n] - bnm[n]*s);
    }
}

// Build frag-packed tf32 weight tiles.
// 0: Wphi | 1: Wg1[0:128]*s | 2: Wg1[128:256]*s | 3: Wu[128:256] | 4: Wu[0:128]
__global__ void prep_kernel(const float* __restrict__ Wphi, const float* __restrict__ Wg1,
                            const float* __restrict__ Wu,
                            const float* __restrict__ bng, const float* __restrict__ bnv)
{
    int mat = blockIdx.x;
    int n = threadIdx.x;
    float s = bng[n] * rsqrtf(bnv[n] + EPS);
    float* bh = g_Wt + mat * DIM * DIM;
    for (int k = 0; k < DIM; k++) {
        float v;
        if      (mat == 0) v = Wphi[k*DIM + n];
        else if (mat == 1) v = Wg1[k*DIM + n] * s;
        else if (mat == 2) v = Wg1[(128+k)*DIM + n] * s;
        else if (mat == 3) v = Wu[(128+k)*DIM + n];
        else               v = Wu[k*DIM + n];
        bh[bpk_idx(k, n)] = __uint_as_float(tf32_rd(v));
    }
}

// store acc tile to half array C (optional bias), rows m0+w*16..
__device__ __forceinline__ void store_tile_h(__half* __restrict__ C, const float acc[16][4],
                                             const float* __restrict__ bias,
                                             int m0, int w, int lane, int M) {
    int r0 = w * 16 + (lane >> 2);
    int gr0 = m0 + r0, gr1 = gr0 + 8;
    #pragma unroll
    for (int nn = 0; nn < 16; nn++) {
        int c0 = nn * 8 + (lane & 3) * 2;
        float bx = 0.f, by = 0.f;
        if (bias) { float2 bb = __ldg((const float2*)(bias + c0)); bx = bb.x; by = bb.y; }
        if (gr0 < M)
            ((__half2*)C)[(size_t)gr0 * 64 + (c0 >> 1)] =
                __floats2half2_rn(acc[nn][0] + bx, acc[nn][1] + by);
        if (gr1 < M)
            ((__half2*)C)[(size_t)gr1 * 64 + (c0 >> 1)] =
                __floats2half2_rn(acc[nn][2] + bx, acc[nn][3] + by);
    }
}

// ---------------------------------------------------------------------------
// Node GEMMs: xj = x@Wphi + bphi; A = x@Wg1a*s; B = x@Wg1b*s  (1x tf32 -> fp16)
// ---------------------------------------------------------------------------
__global__ void __launch_bounds__(256) node_mma(const float* __restrict__ x,
                                               const float* __restrict__ bphi, int M)
{
    extern __shared__ float smf[];
    float* As = smf + SMF_A;
    float* Bh = smf + SMF_BH;
    int t = threadIdx.x, w = t >> 5, lane = t & 31;
    int m0 = blockIdx.x * 128;

    load_A_packed(As, x, t, m0, M);

    float acc[16][4];

    #pragma unroll 1
    for (int mode = 0; mode < 3; mode++) {
        __half* C = (mode == 0) ? g_xjh : (mode == 1 ? g_Ah : g_Bh2);

        __syncthreads();
        copy_B(Bh, g_Wt + mode * DIM * DIM, t);
        __syncthreads();

        #pragma unroll
        for (int i = 0; i < 16; i++) { acc[i][0]=acc[i][1]=acc[i][2]=acc[i][3]=0.f; }
        kloop(acc, As, Bh, w, lane);
        store_tile_h(C, acc, (mode == 0) ? bphi : (const float*)0, m0, w, lane, M);
    }
}

// ---------------------------------------------------------------------------
// Update: h = gelu(agg@Wu_hi + x@Wu_lo + bu); y = x + h; out = LN(y)*lng + lnb
// ---------------------------------------------------------------------------
__global__ void __launch_bounds__(256) update_mma(const float* __restrict__ x,
                                                 const float* __restrict__ bu,
                                                 const float* __restrict__ lng,
                                                 const float* __restrict__ lnb,
                                                 float* __restrict__ out, int M)
{
    extern __shared__ float smf[];
    float* As = smf + SMF_A;
    float* Bh = smf + SMF_BH;
    int t = threadIdx.x, w = t >> 5, lane = t & 31;
    int m0 = blockIdx.x * 128;

    load_A_packed(As, g_agg, t, m0, M);
    copy_B(Bh, g_Wt + 3 * DIM * DIM, t);
    __syncthreads();

    float acc[16][4];
    #pragma unroll
    for (int i = 0; i < 16; i++) { acc[i][0]=acc[i][1]=acc[i][2]=acc[i][3]=0.f; }
    kloop(acc, As, Bh, w, lane);

    __syncthreads();
    load_A_packed(As, x, t, m0, M);
    copy_B(Bh, g_Wt + 4 * DIM * DIM, t);
    __syncthreads();
    kloop(acc, As, Bh, w, lane);

    // epilogue
    int r0 = w * 16 + (lane >> 2);
    int r1 = r0 + 8;
    int gr0 = m0 + r0, gr1 = m0 + r1;
    float s0 = 0.f, q0 = 0.f, s1 = 0.f, q1 = 0.f;

    #pragma unroll
    for (int nn = 0; nn < 16; nn++) {
        int c0 = nn * 8 + (lane & 3) * 2;
        float2 bb = __ldg((const float2*)(bu + c0));
        float y00 = As[apk_idx(r0, c0)]     + gelu_exact(acc[nn][0] + bb.x);
        float y01 = As[apk_idx(r0, c0 + 1)] + gelu_exact(acc[nn][1] + bb.y);
        float y10 = As[apk_idx(r1, c0)]     + gelu_exact(acc[nn][2] + bb.x);
        float y11 = As[apk_idx(r1, c0 + 1)] + gelu_exact(acc[nn][3] + bb.y);
        acc[nn][0] = y00; acc[nn][1] = y01; acc[nn][2] = y10; acc[nn][3] = y11;
        s0 += y00 + y01; q0 += y00*y00 + y01*y01;
        s1 += y10 + y11; q1 += y10*y10 + y11*y11;
    }
    s0 += __shfl_xor_sync(0xffffffffu, s0, 1); s0 += __shfl_xor_sync(0xffffffffu, s0, 2);
    q0 += __shfl_xor_sync(0xffffffffu, q0, 1); q0 += __shfl_xor_sync(0xffffffffu, q0, 2);
    s1 += __shfl_xor_sync(0xffffffffu, s1, 1); s1 += __shfl_xor_sync(0xffffffffu, s1, 2);
    q1 += __shfl_xor_sync(0xffffffffu, q1, 1); q1 += __shfl_xor_sync(0xffffffffu, q1, 2);

    float mu0 = s0 * (1.f / DIM), var0 = q0 * (1.f / DIM) - mu0 * mu0;
    float mu1 = s1 * (1.f / DIM), var1 = q1 * (1.f / DIM) - mu1 * mu1;
    float rs0 = rsqrtf(var0 + EPS), rs1 = rsqrtf(var1 + EPS);

    #pragma unroll
    for (int nn = 0; nn < 16; nn++) {
        int c0 = nn * 8 + (lane & 3) * 2;
        float2 lg = __ldg((const float2*)(lng + c0));
        float2 lb = __ldg((const float2*)(lnb + c0));
        if (gr0 < M)
            *(float2*)(out + (size_t)gr0 * DIM + c0) = make_float2(
                (acc[nn][0] - mu0) * rs0 * lg.x + lb.x,
                (acc[nn][1] - mu0) * rs0 * lg.y + lb.y);
        if (gr1 < M)
            *(float2*)(out + (size_t)gr1 * DIM + c0) = make_float2(
                (acc[nn][2] - mu1) * rs1 * lg.x + lb.x,
                (acc[nn][3] - mu1) * rs1 * lg.y + lb.y);
    }
}

// ---------------------------------------------------------------------------
// Edge kernel: warp per edge, 4-edge unroll; fp16 gathers; RED.v4 scatter.
// ---------------------------------------------------------------------------
__device__ __forceinline__ float4 h4_to_f4(uint2 u) {
    __half2 lo = *(__half2*)&u.x, hi = *(__half2*)&u.y;
    float2 a = __half22float2(lo), b = __half22float2(hi);
    return make_float4(a.x, a.y, b.x, b.y);
}

__global__ void __launch_bounds__(256) edge_kernel(
    const int* __restrict__ ei, const float* __restrict__ ew,
    const float* __restrict__ ef, const float* __restrict__ Wg2,
    const float* __restrict__ bg2, int E)
{
    int lane = threadIdx.x & 31;
    int warp = (blockIdx.x * blockDim.x + threadIdx.x) >> 5;
    int nw   = (gridDim.x * blockDim.x) >> 5;

    float4 we0 = ((const float4*)(g_params          ))[lane];
    float4 we1 = ((const float4*)(g_params +     DIM))[lane];
    float4 cb  = ((const float4*)(g_params + 2 * DIM))[lane];
    float4 w2  = ((const float4*)Wg2)[lane];
    float  b2  = bg2[0];

    const uint2* Ah  = (const uint2*)g_Ah;
    const uint2* Bh  = (const uint2*)g_Bh2;
    const uint2* Xjh = (const uint2*)g_xjh;

    for (int e0 = warp*4; e0 < E; e0 += nw*4) {
        int  ej [4]; bool has[4];
        int  srcj[4], dstj[4];
        float wj[4]; float2 efj[4];
        #pragma unroll
        for (int j = 0; j < 4; j++) {
            ej[j]  = e0 + j;
            has[j] = (ej[j] < E);
            int es = has[j] ? ej[j] : e0;
            srcj[j] = ei[es];
            dstj[j] = ei[E + es];
            wj[j]   = has[j] ? ew[es] : 0.f;
            efj[j]  = ((const float2*)ef)[es];
        }

        uint2 ra[4], rb[4], rx[4];
        #pragma unroll
        for (int j = 0; j < 4; j++) {
            ra[j] = __ldg(Ah  + (size_t)dstj[j]*32 + lane);
            rb[j] = __ldg(Bh  + (size_t)srcj[j]*32 + lane);
            rx[j] = __ldg(Xjh + (size_t)srcj[j]*32 + lane);
        }

        float dj[4];
        #pragma unroll
        for (int j = 0; j < 4; j++) {
            float4 a = h4_to_f4(ra[j]);
            float4 b = h4_to_f4(rb[j]);
            float hx = a.x + b.x + efj[j].x*we0.x + efj[j].y*we1.x + cb.x;
            float hy = a.y + b.y + efj[j].x*we0.y + efj[j].y*we1.y + cb.y;
            float hz = a.z + b.z + efj[j].x*we0.z + efj[j].y*we1.z + cb.z;
            float hw = a.w + b.w + efj[j].x*we0.w + efj[j].y*we1.w + cb.w;
            dj[j] = gelu_fast(hx)*w2.x + gelu_fast(hy)*w2.y
                  + gelu_fast(hz)*w2.z + gelu_fast(hw)*w2.w;
        }

        #pragma unroll
        for (int off = 16; off > 0; off >>= 1) {
            #pragma unroll
            for (int j = 0; j < 4; j++)
                dj[j] += __shfl_xor_sync(0xffffffffu, dj[j], off);
        }

        #pragma unroll
        for (int j = 0; j < 4; j++) {
            if (has[j]) {
                float c = wj[j] / (1.f + __expf(-(dj[j] + b2)));
                float4 xs = h4_to_f4(rx[j]);
                red_add_v4(g_agg + (size_t)dstj[j]*DIM + lane*4,
                           xs.x*c, xs.y*c, xs.z*c, xs.w*c);
            }
        }
    }
}

// ---------------------------------------------------------------------------
extern "C" void kernel_launch(void* const* d_in, const int* in_sizes, int n_in,
                              void* d_out, int out_size)
{
    const float* x    = (const float*)d_in[0];
    const int*   ei   = (const int*)  d_in[1];
    const float* ew   = (const float*)d_in[2];
    const float* ef   = (const float*)d_in[3];
    const float* Wphi = (const float*)d_in[5];
    const float* bphi = (const float*)d_in[6];
    const float* Wg1  = (const float*)d_in[7];
    const float* bg1  = (const float*)d_in[8];
    const float* bng  = (const float*)d_in[9];
    const float* bnb  = (const float*)d_in[10];
    const float* bnm  = (const float*)d_in[11];
    const float* bnv  = (const float*)d_in[12];
    const float* Wg2  = (const float*)d_in[13];
    const float* bg2  = (const float*)d_in[14];
    const float* Wu   = (const float*)d_in[15];
    const float* bu   = (const float*)d_in[16];
    const float* lng  = (const float*)d_in[17];
    const float* lnb  = (const float*)d_in[18];
    float* out = (float*)d_out;

    int M = in_sizes[0] / DIM;
    int E = in_sizes[2];
    if (M > MAXN) return;

    cudaFuncSetAttribute(node_mma,   cudaFuncAttributeMaxDynamicSharedMemorySize, SM_BYTES);
    cudaFuncSetAttribute(update_mma, cudaFuncAttributeMaxDynamicSharedMemorySize, SM_BYTES);

    void* aggp = nullptr;
    cudaGetSymbolAddress(&aggp, g_agg);
    cudaMemsetAsync(aggp, 0, (size_t)M * DIM * sizeof(float), 0);

    param_kernel<<<1, DIM>>>(Wg1, bg1, bng, bnb, bnm, bnv);
    prep_kernel<<<5, DIM>>>(Wphi, Wg1, Wu, bng, bnv);

    int ntiles = (M + 127) / 128;
    node_mma<<<ntiles, 256, SM_BYTES>>>(x, bphi, M);

    edge_kernel<<<2368, 256>>>(ei, ew, ef, Wg2, bg2, E);

    update_mma<<<ntiles, 256, SM_BYTES>>>(x, bu, lng, lnb, out, M);
}

// round 17
// speedup vs baseline: 1.6617x; 1.3754x over previous
#include <cuda_runtime.h>
#include <cuda_fp16.h>
#include <math.h>
#include <stdint.h>

// ---------------------------------------------------------------------------
// EdgeGatedMPNNLayer — GB300 (sm_103a) — Round 17 (R16 + B-tile size fix)
//  * GEMMs: fp16 mma.sync.m16n8k16 (fp32 accum). B frag tile = 8192 u32 =
//    32KB (R16 allocated 16KB -> OOB writes in prep_kernel -> IMA).
//  * Edge kernel: R15 (fp16 gathers, 4-edge unroll, gelu_fast, RED.v4).
// ---------------------------------------------------------------------------

#define DIM 128
#define MAXN 50000
#define EPS 1e-5f

__device__ __half   g_xjh[MAXN*DIM];
__device__ __half   g_Ah [MAXN*DIM];
__device__ __half   g_Bh2[MAXN*DIM];
__device__ float    g_agg[MAXN*DIM];
__device__ float    g_params[3*DIM];       // we0, we1, cbias (edge kernel)
__device__ uint32_t g_Wt[5*8192];          // frag-packed fp16 weight tiles (32KB ea)

// smem u32 offsets
#define SMU_A  0           // A: 8192 u32 = 32KB
#define SMU_B  8192        // B: 8192 u32 = 32KB
#define SM_BYTES (16384*4) // 64KB

// ---------------------------------------------------------------------------
__device__ __forceinline__ float gelu_exact(float v) {
    return 0.5f * v * (1.0f + erff(v * 0.70710678118654752f));
}
__device__ __forceinline__ float gelu_fast(float v) {
    float u = v * fmaf(0.035677408136f, v * v, 0.79788456080f);
    float t;
    asm("tanh.approx.f32 %0, %1;" : "=f"(t) : "f"(u));
    return 0.5f * v * (1.0f + t);
}
__device__ __forceinline__ void red_add_v4(float* p, float a, float b, float c, float d) {
    asm volatile("red.global.add.v4.f32 [%0], {%1,%2,%3,%4};"
                 :: "l"(p), "f"(a), "f"(b), "f"(c), "f"(d) : "memory");
}
__device__ __forceinline__ void mma16(float* d, uint4 a, uint32_t b0, uint32_t b1) {
    asm("mma.sync.aligned.m16n8k16.row.col.f32.f16.f16.f32 "
        "{%0,%1,%2,%3}, {%4,%5,%6,%7}, {%8,%9}, {%0,%1,%2,%3};"
        : "+f"(d[0]), "+f"(d[1]), "+f"(d[2]), "+f"(d[3])
        : "r"(a.x), "r"(a.y), "r"(a.z), "r"(a.w), "r"(b0), "r"(b1));
}
__device__ __forceinline__ uint32_t packh2(float a, float b) {
    __half2 h = __floats2half2_rn(a, b);
    return *(uint32_t*)&h;
}

// fp16 frag-packed u32 index for A element (r, k even): [8 kb][8 mf][32 lane][4 reg]
__device__ __forceinline__ int apk16(int r, int k) {
    return ((((k >> 4) * 8 + (r >> 4)) * 32) + (((r & 7) << 2) | ((k & 7) >> 1))) * 4
         + (((r >> 3) & 1) | (((k >> 3) & 1) << 1));
}
// fp16 frag-packed u32 index for B element (k even, n): [8 kb][8 npair][32 lane][4 reg]
__device__ __forceinline__ int bpk16(int k, int n) {
    return ((((k >> 4) * 8 + (n >> 4)) * 32) + (((n & 7) << 2) | ((k & 7) >> 1))) * 4
         + (((k >> 3) & 1) | (((n >> 3) & 1) << 1));
}

// stage 128-row slab of fp32 row-major src into fp16 frag-packed smem
__device__ __forceinline__ void load_A_packed(uint32_t* As, const float* __restrict__ src,
                                              int t, int m0, int M) {
    #pragma unroll
    for (int i = 0; i < 16; i++) {
        int f = t + i * 256;                 // float4 index 0..4095
        int r = f >> 5, k4 = f & 31;
        float4 v = make_float4(0.f, 0.f, 0.f, 0.f);
        int gr = m0 + r;
        if (gr < M) v = ((const float4*)src)[(size_t)gr * 32 + k4];
        int k0 = k4 * 4;
        int idx = apk16(r, k0);
        As[idx]     = packh2(v.x, v.y);
        As[idx + 4] = packh2(v.z, v.w);      // k0+2,k0+3: next lane slot, same reg
    }
}
// flat copy of a pre-packed 32KB weight tile (2048 uint4)
__device__ __forceinline__ void copy_B(uint32_t* dst, const uint32_t* __restrict__ gsrc, int t) {
    const uint4* s = (const uint4*)gsrc;
    uint4* d = (uint4*)dst;
    #pragma unroll
    for (int i = 0; i < 8; i++) d[t + i * 256] = s[t + i * 256];
}

// K-loop: warp w computes rows w*16..+15 x all 128 cols. fp16 m16n8k16.
__device__ __forceinline__ void kloop16(float acc[16][4], const uint32_t* As,
                                        const uint32_t* Bs, int w, int lane) {
    #pragma unroll
    for (int kb = 0; kb < 8; kb++) {
        uint4 av = ((const uint4*)As)[(kb * 8 + w) * 32 + lane];
        #pragma unroll
        for (int np = 0; np < 8; np++) {
            uint4 bv = ((const uint4*)Bs)[(kb * 8 + np) * 32 + lane];
            mma16(acc[2*np],     av, bv.x, bv.y);
            mma16(acc[2*np + 1], av, bv.z, bv.w);
        }
    }
}

// ---------------------------------------------------------------------------
__global__ void param_kernel(const float* __restrict__ Wg1, const float* __restrict__ bg1,
                             const float* __restrict__ bng, const float* __restrict__ bnb,
                             const float* __restrict__ bnm, const float* __restrict__ bnv)
{
    int n = threadIdx.x;
    if (n < DIM) {
        float s = bng[n] * rsqrtf(bnv[n] + EPS);
        g_params[n]         = Wg1[256*DIM + n] * s;
        g_params[DIM + n]   = Wg1[257*DIM + n] * s;
        g_params[2*DIM + n] = bg1[n]*s + (bnb[n] - bnm[n]*s);
    }
}

// Build frag-packed fp16 weight tiles. v(k,n) per mat:
// 0: Wphi | 1: Wg1[0:128]*s | 2: Wg1[128:256]*s | 3: Wu[128:256] | 4: Wu[0:128]
__global__ void prep_kernel(const float* __restrict__ Wphi, const float* __restrict__ Wg1,
                            const float* __restrict__ Wu,
                            const float* __restrict__ bng, const float* __restrict__ bnv)
{
    int mat = blockIdx.x;
    int n = threadIdx.x;
    float s = bng[n] * rsqrtf(bnv[n] + EPS);
    uint32_t* bh = g_Wt + mat * 8192;
    for (int k = 0; k < DIM; k += 2) {
        float v0, v1;
        if      (mat == 0) { v0 = Wphi[k*DIM + n];           v1 = Wphi[(k+1)*DIM + n]; }
        else if (mat == 1) { v0 = Wg1[k*DIM + n] * s;        v1 = Wg1[(k+1)*DIM + n] * s; }
        else if (mat == 2) { v0 = Wg1[(128+k)*DIM + n] * s;  v1 = Wg1[(129+k)*DIM + n] * s; }
        else if (mat == 3) { v0 = Wu[(128+k)*DIM + n];       v1 = Wu[(129+k)*DIM + n]; }
        else               { v0 = Wu[k*DIM + n];             v1 = Wu[(k+1)*DIM + n]; }
        bh[bpk16(k, n)] = packh2(v0, v1);
    }
}

// store acc tile to half array C (optional bias), rows m0+w*16..
__device__ __forceinline__ void store_tile_h(__half* __restrict__ C, const float acc[16][4],
                                             const float* __restrict__ bias,
                                             int m0, int w, int lane, int M) {
    int r0 = w * 16 + (lane >> 2);
    int gr0 = m0 + r0, gr1 = gr0 + 8;
    #pragma unroll
    for (int nn = 0; nn < 16; nn++) {
        int c0 = nn * 8 + (lane & 3) * 2;
        float bx = 0.f, by = 0.f;
        if (bias) { float2 bb = __ldg((const float2*)(bias + c0)); bx = bb.x; by = bb.y; }
        if (gr0 < M)
            ((__half2*)C)[(size_t)gr0 * 64 + (c0 >> 1)] =
                __floats2half2_rn(acc[nn][0] + bx, acc[nn][1] + by);
        if (gr1 < M)
            ((__half2*)C)[(size_t)gr1 * 64 + (c0 >> 1)] =
                __floats2half2_rn(acc[nn][2] + bx, acc[nn][3] + by);
    }
}

// ---------------------------------------------------------------------------
// Node GEMMs: xj = x@Wphi + bphi; A = x@Wg1a*s; B = x@Wg1b*s  (fp16 MMA)
// ---------------------------------------------------------------------------
__global__ void __launch_bounds__(256) node_mma(const float* __restrict__ x,
                                               const float* __restrict__ bphi, int M)
{
    extern __shared__ uint32_t smu[];
    uint32_t* As = smu + SMU_A;
    uint32_t* Bs = smu + SMU_B;
    int t = threadIdx.x, w = t >> 5, lane = t & 31;
    int m0 = blockIdx.x * 128;

    load_A_packed(As, x, t, m0, M);

    float acc[16][4];

    #pragma unroll 1
    for (int mode = 0; mode < 3; mode++) {
        __half* C = (mode == 0) ? g_xjh : (mode == 1 ? g_Ah : g_Bh2);

        __syncthreads();                 // As ready / previous kloop done
        copy_B(Bs, g_Wt + mode * 8192, t);
        __syncthreads();

        #pragma unroll
        for (int i = 0; i < 16; i++) { acc[i][0]=acc[i][1]=acc[i][2]=acc[i][3]=0.f; }
        kloop16(acc, As, Bs, w, lane);
        store_tile_h(C, acc, (mode == 0) ? bphi : (const float*)0, m0, w, lane, M);
    }
}

// ---------------------------------------------------------------------------
// Update: h = gelu(agg@Wu_hi + x@Wu_lo + bu); y = x + h; out = LN(y)*lng + lnb
// Residual x re-read from gmem fp32 (L2-hot) — not fp16-quantized.
// ---------------------------------------------------------------------------
__global__ void __launch_bounds__(256) update_mma(const float* __restrict__ x,
                                                 const float* __restrict__ bu,
                                                 const float* __restrict__ lng,
                                                 const float* __restrict__ lnb,
                                                 float* __restrict__ out, int M)
{
    extern __shared__ uint32_t smu[];
    uint32_t* As = smu + SMU_A;
    uint32_t* Bs = smu + SMU_B;
    int t = threadIdx.x, w = t >> 5, lane = t & 31;
    int m0 = blockIdx.x * 128;

    load_A_packed(As, g_agg, t, m0, M);
    copy_B(Bs, g_Wt + 3 * 8192, t);
    __syncthreads();

    float acc[16][4];
    #pragma unroll
    for (int i = 0; i < 16; i++) { acc[i][0]=acc[i][1]=acc[i][2]=acc[i][3]=0.f; }
    kloop16(acc, As, Bs, w, lane);

    __syncthreads();
    load_A_packed(As, x, t, m0, M);
    copy_B(Bs, g_Wt + 4 * 8192, t);
    __syncthreads();
    kloop16(acc, As, Bs, w, lane);

    // epilogue: residual x from gmem (fp32), LN per row
    int r0 = w * 16 + (lane >> 2);
    int r1 = r0 + 8;
    int gr0 = m0 + r0, gr1 = m0 + r1;
    float s0 = 0.f, q0 = 0.f, s1 = 0.f, q1 = 0.f;

    #pragma unroll
    for (int nn = 0; nn < 16; nn++) {
        int c0 = nn * 8 + (lane & 3) * 2;
        float2 bb = __ldg((const float2*)(bu + c0));
        float2 xv0 = make_float2(0.f, 0.f), xv1 = make_float2(0.f, 0.f);
        if (gr0 < M) xv0 = __ldg((const float2*)(x + (size_t)gr0 * DIM + c0));
        if (gr1 < M) xv1 = __ldg((const float2*)(x + (size_t)gr1 * DIM + c0));
        float y00 = xv0.x + gelu_exact(acc[nn][0] + bb.x);
        float y01 = xv0.y + gelu_exact(acc[nn][1] + bb.y);
        float y10 = xv1.x + gelu_exact(acc[nn][2] + bb.x);
        float y11 = xv1.y + gelu_exact(acc[nn][3] + bb.y);
        acc[nn][0] = y00; acc[nn][1] = y01; acc[nn][2] = y10; acc[nn][3] = y11;
        s0 += y00 + y01; q0 += y00*y00 + y01*y01;
        s1 += y10 + y11; q1 += y10*y10 + y11*y11;
    }
    s0 += __shfl_xor_sync(0xffffffffu, s0, 1); s0 += __shfl_xor_sync(0xffffffffu, s0, 2);
    q0 += __shfl_xor_sync(0xffffffffu, q0, 1); q0 += __shfl_xor_sync(0xffffffffu, q0, 2);
    s1 += __shfl_xor_sync(0xffffffffu, s1, 1); s1 += __shfl_xor_sync(0xffffffffu, s1, 2);
    q1 += __shfl_xor_sync(0xffffffffu, q1, 1); q1 += __shfl_xor_sync(0xffffffffu, q1, 2);

    float mu0 = s0 * (1.f / DIM), var0 = q0 * (1.f / DIM) - mu0 * mu0;
    float mu1 = s1 * (1.f / DIM), var1 = q1 * (1.f / DIM) - mu1 * mu1;
    float rs0 = rsqrtf(var0 + EPS), rs1 = rsqrtf(var1 + EPS);

    #pragma unroll
    for (int nn = 0; nn < 16; nn++) {
        int c0 = nn * 8 + (lane & 3) * 2;
        float2 lg = __ldg((const float2*)(lng + c0));
        float2 lb = __ldg((const float2*)(lnb + c0));
        if (gr0 < M)
            *(float2*)(out + (size_t)gr0 * DIM + c0) = make_float2(
                (acc[nn][0] - mu0) * rs0 * lg.x + lb.x,
                (acc[nn][1] - mu0) * rs0 * lg.y + lb.y);
        if (gr1 < M)
            *(float2*)(out + (size_t)gr1 * DIM + c0) = make_float2(
                (acc[nn][2] - mu1) * rs1 * lg.x + lb.x,
                (acc[nn][3] - mu1) * rs1 * lg.y + lb.y);
    }
}

// ---------------------------------------------------------------------------
// Edge kernel: warp per edge, 4-edge unroll; fp16 gathers; RED.v4 scatter.
// ---------------------------------------------------------------------------
__device__ __forceinline__ float4 h4_to_f4(uint2 u) {
    __half2 lo = *(__half2*)&u.x, hi = *(__half2*)&u.y;
    float2 a = __half22float2(lo), b = __half22float2(hi);
    return make_float4(a.x, a.y, b.x, b.y);
}

__global__ void __launch_bounds__(256) edge_kernel(
    const int* __restrict__ ei, const float* __restrict__ ew,
    const float* __restrict__ ef, const float* __restrict__ Wg2,
    const float* __restrict__ bg2, int E)
{
    int lane = threadIdx.x & 31;
    int warp = (blockIdx.x * blockDim.x + threadIdx.x) >> 5;
    int nw   = (gridDim.x * blockDim.x) >> 5;

    float4 we0 = ((const float4*)(g_params          ))[lane];
    float4 we1 = ((const float4*)(g_params +     DIM))[lane];
    float4 cb  = ((const float4*)(g_params + 2 * DIM))[lane];
    float4 w2  = ((const float4*)Wg2)[lane];
    float  b2  = bg2[0];

    const uint2* Ah  = (const uint2*)g_Ah;
    const uint2* Bh  = (const uint2*)g_Bh2;
    const uint2* Xjh = (const uint2*)g_xjh;

    for (int e0 = warp*4; e0 < E; e0 += nw*4) {
        bool has[4];
        int  srcj[4], dstj[4];
        float wj[4]; float2 efj[4];
        #pragma unroll
        for (int j = 0; j < 4; j++) {
            int e = e0 + j;
            has[j] = (e < E);
            int es = has[j] ? e : e0;
            srcj[j] = ei[es];
            dstj[j] = ei[E + es];
            wj[j]   = has[j] ? ew[es] : 0.f;
            efj[j]  = ((const float2*)ef)[es];
        }

        uint2 ra[4], rb[4], rx[4];
        #pragma unroll
        for (int j = 0; j < 4; j++) {
            ra[j] = __ldg(Ah  + (size_t)dstj[j]*32 + lane);
            rb[j] = __ldg(Bh  + (size_t)srcj[j]*32 + lane);
            rx[j] = __ldg(Xjh + (size_t)srcj[j]*32 + lane);
        }

        float dj[4];
        #pragma unroll
        for (int j = 0; j < 4; j++) {
            float4 a = h4_to_f4(ra[j]);
            float4 b = h4_to_f4(rb[j]);
            float hx = a.x + b.x + efj[j].x*we0.x + efj[j].y*we1.x + cb.x;
            float hy = a.y + b.y + efj[j].x*we0.y + efj[j].y*we1.y + cb.y;
            float hz = a.z + b.z + efj[j].x*we0.z + efj[j].y*we1.z + cb.z;
            float hw = a.w + b.w + efj[j].x*we0.w + efj[j].y*we1.w + cb.w;
            dj[j] = gelu_fast(hx)*w2.x + gelu_fast(hy)*w2.y
                  + gelu_fast(hz)*w2.z + gelu_fast(hw)*w2.w;
        }

        #pragma unroll
        for (int off = 16; off > 0; off >>= 1) {
            #pragma unroll
            for (int j = 0; j < 4; j++)
                dj[j] += __shfl_xor_sync(0xffffffffu, dj[j], off);
        }

        #pragma unroll
        for (int j = 0; j < 4; j++) {
            if (has[j]) {
                float c = wj[j] / (1.f + __expf(-(dj[j] + b2)));
                float4 xs = h4_to_f4(rx[j]);
                red_add_v4(g_agg + (size_t)dstj[j]*DIM + lane*4,
                           xs.x*c, xs.y*c, xs.z*c, xs.w*c);
            }
        }
    }
}

// ---------------------------------------------------------------------------
extern "C" void kernel_launch(void* const* d_in, const int* in_sizes, int n_in,
                              void* d_out, int out_size)
{
    const float* x    = (const float*)d_in[0];
    const int*   ei   = (const int*)  d_in[1];
    const float* ew   = (const float*)d_in[2];
    const float* ef   = (const float*)d_in[3];
    const float* Wphi = (const float*)d_in[5];
    const float* bphi = (const float*)d_in[6];
    const float* Wg1  = (const float*)d_in[7];
    const float* bg1  = (const float*)d_in[8];
    const float* bng  = (const float*)d_in[9];
    const float* bnb  = (const float*)d_in[10];
    const float* bnm  = (const float*)d_in[11];
    const float* bnv  = (const float*)d_in[12];
    const float* Wg2  = (const float*)d_in[13];
    const float* bg2  = (const float*)d_in[14];
    const float* Wu   = (const float*)d_in[15];
    const float* bu   = (const float*)d_in[16];
    const float* lng  = (const float*)d_in[17];
    const float* lnb  = (const float*)d_in[18];
    float* out = (float*)d_out;

    int M = in_sizes[0] / DIM;
    int E = in_sizes[2];
    if (M > MAXN) return;

    cudaFuncSetAttribute(node_mma,   cudaFuncAttributeMaxDynamicSharedMemorySize, SM_BYTES);
    cudaFuncSetAttribute(update_mma, cudaFuncAttributeMaxDynamicSharedMemorySize, SM_BYTES);

    void* aggp = nullptr;
    cudaGetSymbolAddress(&aggp, g_agg);
    cudaMemsetAsync(aggp, 0, (size_t)M * DIM * sizeof(float), 0);

    param_kernel<<<1, DIM>>>(Wg1, bg1, bng, bnb, bnm, bnv);
    prep_kernel<<<5, DIM>>>(Wphi, Wg1, Wu, bng, bnv);

    int ntiles = (M + 127) / 128;
    node_mma<<<ntiles, 256, SM_BYTES>>>(x, bphi, M);

    edge_kernel<<<2368, 256>>>(ei, ew, ef, Wg2, bg2, E);

    update_mma<<<ntiles, 256, SM_BYTES>>>(x, bu, lng, lnb, out, M);
}